// round 1
// baseline (speedup 1.0000x reference)
#include <cuda_runtime.h>
#include <cstddef>

#define BSZ   8192
#define DIMN  100
#define NSTEP 49
#define WH    256
#define RRATE 0.05f

// ---------------- device scratch (static, no allocations) ----------------
__device__ float g_volpre[(size_t)NSTEP * BSZ * DIMN]; // 160.6 MB
__device__ float g_Vt[DIMN * DIMN];
__device__ float g_Sbuf[2][BSZ * DIMN];
__device__ float g_hbuf[2][BSZ * WH];
__device__ float g_grad[BSZ * DIMN];
__device__ float g_vbuf[2][BSZ];
__device__ float g_stoch[BSZ];
__device__ float g_err[BSZ];

// ---------------- packed fp32x2 FMA (sm_100+/sm_103a FFMA2) ----------------
__device__ __forceinline__ float2 ffma2(float2 a, float2 b, float2 c) {
    float2 d;
    asm("fma.rn.f32x2 %0, %1, %2, %3;"
        : "=l"(*reinterpret_cast<unsigned long long*>(&d))
        : "l"(*reinterpret_cast<unsigned long long*>(&a)),
          "l"(*reinterpret_cast<unsigned long long*>(&b)),
          "l"(*reinterpret_cast<unsigned long long*>(&c)));
    return d;
}

// ---------------- generic GEMM: C = act(A[M,K] @ W[K,N] + bias + t*w0) ----
// BM=128, BN=64, BK=16, 256 threads, 8x4 per thread (packed as 4 row-pairs).
// Requires: M % 128 == 0, K % 4 == 0, N % 4 == 0 (all shapes here satisfy).
__global__ __launch_bounds__(256) void gemm_kernel(
    const float* __restrict__ A, const float* __restrict__ W,
    const float* __restrict__ bias, const float* __restrict__ w0,
    const float* __restrict__ tg, int tIdx,
    float* __restrict__ C, int M, int N, int K, int relu)
{
    __shared__ __align__(16) float As[16][128];
    __shared__ __align__(16) float Bs[16][64];

    const int tid = threadIdx.x;
    const int tx = tid & 15;        // 16 cols of 4  -> BN=64
    const int ty = tid >> 4;        // 16 rows of 8  -> BM=128
    const int mBase = blockIdx.y * 128;
    const int nBase = blockIdx.x * 64;

    float2 acc[4][4];
#pragma unroll
    for (int i = 0; i < 4; ++i)
#pragma unroll
        for (int j = 0; j < 4; ++j) acc[i][j] = make_float2(0.f, 0.f);

    const int nTiles = (K + 15) >> 4;
    for (int kt = 0; kt < nTiles; ++kt) {
        const int k0 = kt << 4;
        // load A tile [128 x 16] (transposed into smem)
#pragma unroll
        for (int i = 0; i < 2; ++i) {
            int idx = tid + i * 256;           // 0..511 float4 slots
            int r  = idx >> 2;                 // row 0..127
            int c4 = (idx & 3) << 2;           // col 0,4,8,12
            int gc = k0 + c4;
            float4 v = make_float4(0.f, 0.f, 0.f, 0.f);
            if (gc < K)                        // K%4==0 -> float4 fully valid
                v = *(const float4*)(A + (size_t)(mBase + r) * K + gc);
            As[c4 + 0][r] = v.x; As[c4 + 1][r] = v.y;
            As[c4 + 2][r] = v.z; As[c4 + 3][r] = v.w;
        }
        // load W tile [16 x 64]
        {
            int k  = tid >> 4;                 // 0..15
            int c4 = (tid & 15) << 2;          // 0..60
            int gk = k0 + k, gn = nBase + c4;
            float4 v = make_float4(0.f, 0.f, 0.f, 0.f);
            if (gk < K && gn < N)              // N%4==0
                v = *(const float4*)(W + (size_t)gk * N + gn);
            *(float4*)&Bs[k][c4] = v;
        }
        __syncthreads();

#pragma unroll
        for (int k = 0; k < 16; ++k) {
            float4 aLo = *(const float4*)&As[k][ty * 8];
            float4 aHi = *(const float4*)&As[k][ty * 8 + 4];
            float4 bv  = *(const float4*)&Bs[k][tx * 4];
            float2 a2[4] = { make_float2(aLo.x, aLo.y), make_float2(aLo.z, aLo.w),
                             make_float2(aHi.x, aHi.y), make_float2(aHi.z, aHi.w) };
            float  bs[4] = { bv.x, bv.y, bv.z, bv.w };
#pragma unroll
            for (int j = 0; j < 4; ++j) {
                float2 bb = make_float2(bs[j], bs[j]);
#pragma unroll
                for (int mp = 0; mp < 4; ++mp)
                    acc[mp][j] = ffma2(a2[mp], bb, acc[mp][j]);
            }
        }
        __syncthreads();
    }

    // epilogue
    const int n0 = nBase + tx * 4;
    if (n0 >= N) return;
    float4 bb = make_float4(0.f, 0.f, 0.f, 0.f);
    if (bias) bb = *(const float4*)(bias + n0);
    if (w0) {                                   // fold t-column of input layer
        float t = __ldg(tg + tIdx);
        float4 wv = *(const float4*)(w0 + n0);
        bb.x += t * wv.x; bb.y += t * wv.y; bb.z += t * wv.z; bb.w += t * wv.w;
    }
#pragma unroll
    for (int mp = 0; mp < 4; ++mp) {
#pragma unroll
        for (int half = 0; half < 2; ++half) {
            int m = mBase + ty * 8 + mp * 2 + half;
            float4 o;
            o.x = (half ? acc[mp][0].y : acc[mp][0].x) + bb.x;
            o.y = (half ? acc[mp][1].y : acc[mp][1].x) + bb.y;
            o.z = (half ? acc[mp][2].y : acc[mp][2].x) + bb.z;
            o.w = (half ? acc[mp][3].y : acc[mp][3].x) + bb.w;
            if (relu) {
                o.x = fmaxf(o.x, 0.f); o.y = fmaxf(o.y, 0.f);
                o.z = fmaxf(o.z, 0.f); o.w = fmaxf(o.w, 0.f);
            }
            *(float4*)(C + (size_t)m * N + n0) = o;
        }
    }
}

// ---------------- V transpose (100x100) ----------------
__global__ void transpose_kernel(const float* __restrict__ V, float* __restrict__ Vt) {
    for (int i = threadIdx.x + blockIdx.x * 256; i < DIMN * DIMN; i += gridDim.x * 256) {
        int d = i / DIMN, j = i % DIMN;
        Vt[j * DIMN + d] = V[i];
    }
}

// ---------------- GEMV: out[b] = H[b,:]·w + b0  (N=1 output layer) ----------
__global__ __launch_bounds__(256) void gemv_kernel(
    const float* __restrict__ H, const float* __restrict__ w,
    const float* __restrict__ b, float* __restrict__ out)
{
    __shared__ __align__(16) float ws[WH];
    ws[threadIdx.x] = w[threadIdx.x];
    __syncthreads();
    int warp = threadIdx.x >> 5, lane = threadIdx.x & 31;
    int row = blockIdx.x * 8 + warp;
    const float4* hr = (const float4*)(H + (size_t)row * WH);
    const float4* wr = (const float4*)ws;
    float acc = 0.f;
#pragma unroll
    for (int q = 0; q < 2; ++q) {
        float4 h4 = hr[q * 32 + lane];
        float4 w4 = wr[q * 32 + lane];
        acc += h4.x * w4.x + h4.y * w4.y + h4.z * w4.z + h4.w * w4.w;
    }
#pragma unroll
    for (int o = 16; o; o >>= 1) acc += __shfl_xor_sync(0xffffffffu, acc, o);
    if (lane == 0) out[row] = acc + b[0];
}

// ---------------- step: vol, stoch_int, S update ----------------
__global__ __launch_bounds__(256) void step_kernel(
    const float* __restrict__ S_old, const float* __restrict__ vp,
    const float* __restrict__ grad, const float* __restrict__ tg, int i,
    float* __restrict__ S_new, float* __restrict__ stoch)
{
    int warp = threadIdx.x >> 5, lane = threadIdx.x & 31;
    int b = blockIdx.x * 8 + warp;
    float h  = tg[i + 1] - tg[i];
    float sq = sqrtf(h);
    float rh = RRATE * h;
    const float* Sr = S_old + (size_t)b * DIMN;
    const float* vr = vp   + (size_t)b * DIMN;
    const float* gr = grad + (size_t)b * DIMN;
    float acc = 0.f;
    for (int d = lane; d < DIMN; d += 32) {
        float s   = Sr[d];
        float vol = s * (vr[d] * sq);
        acc += gr[d] * vol;
        S_new[(size_t)b * DIMN + d] = s + rh * s + vol;
    }
#pragma unroll
    for (int o = 16; o; o >>= 1) acc += __shfl_xor_sync(0xffffffffu, acc, o);
    if (lane == 0) stoch[b] = acc;
}

// ---------------- error accumulation ----------------
__global__ void err_kernel(const float* __restrict__ vNew, const float* __restrict__ vOld,
                           const float* __restrict__ stoch, const float* __restrict__ tg,
                           int i, float* __restrict__ err)
{
    int b = blockIdx.x * blockDim.x + threadIdx.x;
    if (b >= BSZ) return;
    float h = tg[i + 1] - tg[i];
    float e = vNew[b] - vOld[b] * (1.f + RRATE * h) - stoch[b];
    err[b] += e * e;
}

// ---------------- output packing: [v_f | S_f | error] ----------------
__global__ void pack_kernel(const float* __restrict__ v, const float* __restrict__ S,
                            const float* __restrict__ err, float* __restrict__ out)
{
    int i = blockIdx.x * 256 + threadIdx.x;
    if (i < BSZ * DIMN) out[BSZ + i] = S[i];
    if (i < BSZ) {
        out[i] = v[i];
        out[BSZ + BSZ * DIMN + i] = err[i];
    }
}

// ---------------- host-side helpers ----------------
static void gemm(const float* A, const float* W, const float* bias, const float* w0,
                 const float* tg, int tIdx, float* C, int M, int N, int K, int relu)
{
    dim3 grid((N + 63) / 64, M / 128);
    gemm_kernel<<<grid, 256>>>(A, W, bias, w0, tg, tIdx, C, M, N, K, relu);
}

// Runs input layer (t folded into bias) + 3 hidden layers; result lands in h1.
static void mlp_trunk(const float* X, const float* Win, const float* bin,
                      const float* Wh, const float* bh,
                      const float* tg, int tIdx, float* h0, float* h1)
{
    gemm(X,  Win + WH,        bin,           Win,     tg, tIdx, h0, BSZ, WH, DIMN, 1);
    gemm(h0, Wh + 0 * WH * WH, bh + 0 * WH,  nullptr, nullptr, 0, h1, BSZ, WH, WH, 1);
    gemm(h1, Wh + 1 * WH * WH, bh + 1 * WH,  nullptr, nullptr, 0, h0, BSZ, WH, WH, 1);
    gemm(h0, Wh + 2 * WH * WH, bh + 2 * WH,  nullptr, nullptr, 0, h1, BSZ, WH, WH, 1);
}

extern "C" void kernel_launch(void* const* d_in, const int* in_sizes, int n_in,
                              void* d_out, int out_size)
{
    const float* S0     = (const float*)d_in[0];
    const float* dW     = (const float*)d_in[1];
    const float* tg     = (const float*)d_in[2];
    const float* Vm     = (const float*)d_in[3];
    const float* Wg_in  = (const float*)d_in[4];
    const float* bg_in  = (const float*)d_in[5];
    const float* Wg_h   = (const float*)d_in[6];
    const float* bg_h   = (const float*)d_in[7];
    const float* Wg_out = (const float*)d_in[8];
    const float* bg_out = (const float*)d_in[9];
    const float* Wv_in  = (const float*)d_in[10];
    const float* bv_in  = (const float*)d_in[11];
    const float* Wv_h   = (const float*)d_in[12];
    const float* bv_h   = (const float*)d_in[13];
    const float* Wv_out = (const float*)d_in[14];
    const float* bv_out = (const float*)d_in[15];

    float *volpre, *Vt, *Sb, *hb, *grad, *vb, *stoch, *err;
    cudaGetSymbolAddress((void**)&volpre, g_volpre);
    cudaGetSymbolAddress((void**)&Vt,     g_Vt);
    cudaGetSymbolAddress((void**)&Sb,     g_Sbuf);
    cudaGetSymbolAddress((void**)&hb,     g_hbuf);
    cudaGetSymbolAddress((void**)&grad,   g_grad);
    cudaGetSymbolAddress((void**)&vb,     g_vbuf);
    cudaGetSymbolAddress((void**)&stoch,  g_stoch);
    cudaGetSymbolAddress((void**)&err,    g_err);

    float* Sbuf0 = Sb;
    float* Sbuf1 = Sb + (size_t)BSZ * DIMN;
    float* h0 = hb;
    float* h1 = hb + (size_t)BSZ * WH;
    float* vA = vb;
    float* vBp = vb + BSZ;

    cudaMemsetAsync(err, 0, BSZ * sizeof(float));

    // vol precompute: volpre = dW @ V^T as one big GEMM (sqrt(dt) folded into step)
    transpose_kernel<<<40, 256>>>(Vm, Vt);
    gemm(dW, Vt, nullptr, nullptr, nullptr, 0, volpre, NSTEP * BSZ, DIMN, DIMN, 0);

    // v0 = MLP_v([t0, S0])
    mlp_trunk(S0, Wv_in, bv_in, Wv_h, bv_h, tg, 0, h0, h1);
    gemv_kernel<<<BSZ / 8, 256>>>(h1, Wv_out, bv_out, vA);

    const float* Scur = S0;
    float* vOld = vA;
    float* vNew = vBp;
    int sflip = 0;
    for (int i = 0; i < NSTEP; ++i) {
        // grad = MLP_g([t_i, S_old])
        mlp_trunk(Scur, Wg_in, bg_in, Wg_h, bg_h, tg, i, h0, h1);
        gemm(h1, Wg_out, bg_out, nullptr, nullptr, 0, grad, BSZ, DIMN, WH, 0);
        // vol / stoch_int / S_new
        float* Snew = sflip ? Sbuf1 : Sbuf0;
        step_kernel<<<BSZ / 8, 256>>>(Scur, volpre + (size_t)i * BSZ * DIMN,
                                      grad, tg, i, Snew, stoch);
        // vNew = MLP_v([t_{i+1}, S_new])
        mlp_trunk(Snew, Wv_in, bv_in, Wv_h, bv_h, tg, i + 1, h0, h1);
        gemv_kernel<<<BSZ / 8, 256>>>(h1, Wv_out, bv_out, vNew);
        // error accumulation
        err_kernel<<<BSZ / 256, 256>>>(vNew, vOld, stoch, tg, i, err);

        Scur = Snew; sflip ^= 1;
        float* t = vOld; vOld = vNew; vNew = t;
    }

    // output: [v_f (8192) | S_f (8192*100) | error (8192)]
    pack_kernel<<<(BSZ * DIMN) / 256, 256>>>(vOld, Scur, err, (float*)d_out);
}